// round 13
// baseline (speedup 1.0000x reference)
#include <cuda_runtime.h>
#include <cuda_fp16.h>
#include <cstdint>

// ---------------- problem constants ----------------
#define BATCHB   4
#define NANCH    230400        // 160*160*9
#define NQUAD    (NANCH/4)     // 57600 float4 quads per image (225 blocks * 256 exact)
#define CAP      2048          // candidate capacity per image
#define NW       (CAP/32)      // 64 bitmap words
#define PCAP     4096          // conflict-pair capacity per image (~15x expected)
#define MAXD     1000
#define IMGW     1280.0f
#define TH_IOU   0.5f
#define ZTH      2.45f         // raw objectness gather threshold (sigmoid monotone)
#define NT       256

// ---------------- device scratch (no allocations allowed) ----------------
// g_meta: {key_lo, key_hi, half2(x1,y1) rounded-down, half2(x2,y2) rounded-up}
// zero-init padding is inert: key=0 never outranks, zero box never passes prefilter.
__device__ uint4    g_meta [BATCHB][CAP];
__device__ float4   g_boxes[BATCHB][CAP];             // fp32 decoded boxes
__device__ float    g_area [BATCHB][CAP];
__device__ float    g_score[BATCHB][CAP];
__device__ int      g_rank [BATCHB][CAP];             // rank (0 = best) per unsorted slot
__device__ unsigned g_pairs[BATCHB][PCAP];            // (i<<16)|j, key_i > key_j (i = suppressor)
__device__ int      g_counters[8];                    // [0..3] cand, [4..7] pairs (zero-init; k_scan resets)

// ---------------- helpers ----------------
__device__ __forceinline__ float4 decode_box(float4 d, float4 a) {
    float w  = a.z - a.x;
    float h  = a.w - a.y;
    float cx = a.x + 0.5f * w;
    float cy = a.y + 0.5f * h;
    float px = fmaf(d.x, w, cx);
    float py = fmaf(d.y, h, cy);
    float pw = expf(fminf(d.z, 4.0f)) * w;
    float ph = expf(fminf(d.w, 4.0f)) * h;
    float x1 = px - 0.5f * pw;
    float y1 = py - 0.5f * ph;
    float x2 = px + 0.5f * pw;
    float y2 = py + 0.5f * ph;
    x1 = fminf(fmaxf(x1, 0.0f), IMGW);
    x2 = fminf(fmaxf(x2, 0.0f), IMGW);
    y1 = fminf(fmaxf(y1, 0.0f), IMGW);
    y2 = fminf(fmaxf(y2, 0.0f), IMGW);
    return make_float4(x1, y1, x2, y2);
}

__device__ __forceinline__ float box_area(float4 b) {
    return fmaxf(b.z - b.x, 0.0f) * fmaxf(b.w - b.y, 0.0f);
}

// exact reference IoU decision: inter/(aA + aB - inter + 1e-9) > 0.5
// A/aA MUST be the suppressor (earlier-ranked) box to match operand order.
__device__ __forceinline__ bool conflict_ref(float4 A, float aA, float4 B, float aB) {
    float ix1 = fmaxf(A.x, B.x);
    float iy1 = fmaxf(A.y, B.y);
    float ix2 = fminf(A.z, B.z);
    float iy2 = fminf(A.w, B.w);
    float iw = ix2 - ix1, ih = iy2 - iy1;
    if (iw > 0.0f && ih > 0.0f) {
        float inter = iw * ih;
        return (inter / (aA + aB - inter + 1e-9f)) > TH_IOU;
    }
    return false;
}

// XLA expands lax.logistic as 0.5 + 0.5*tanh(0.5*x)
__device__ __forceinline__ float sigmoid_xla(float x) {
    return 0.5f + 0.5f * tanhf(0.5f * x);
}

// ---------------- kernel 1: gather + decode (4 anchors/thread, float4 reads) ----------------
__global__ void __launch_bounds__(256) k_gather(
    const float* __restrict__ obj,
    const float* __restrict__ deltas,
    const float* __restrict__ anchors)
{
    int b  = blockIdx.y;
    int q  = blockIdx.x * blockDim.x + threadIdx.x;   // quad index (exact fit 225*256)
    float4 xs = reinterpret_cast<const float4*>(obj + (long)b * NANCH)[q];
    float xv[4] = {xs.x, xs.y, xs.z, xs.w};

    #pragma unroll
    for (int k = 0; k < 4; ++k) {
        float x = xv[k];
        if (x <= ZTH) continue;
        int i = q * 4 + k;
        long base = ((long)b * NANCH + i);
        float4 d = reinterpret_cast<const float4*>(deltas)[base];
        float4 a = reinterpret_cast<const float4*>(anchors)[base];
        float4 bx = decode_box(d, a);
        if ((bx.z - bx.x >= 1.0f) && (bx.w - bx.y >= 1.0f)) {
            float s = sigmoid_xla(x);
            unsigned sb = __float_as_uint(s);       // positive float: bits monotone
            unsigned long long key =
                ((unsigned long long)sb << 18) | (unsigned long long)(0x3FFFFu - (unsigned)i);
            int p = atomicAdd(&g_counters[b], 1);
            if (p < CAP) {
                // conservative fp16 box: lo rounded down, hi rounded up
                __half2 p01 = __halves2half2(__float2half_rd(bx.x), __float2half_rd(bx.y));
                __half2 p23 = __halves2half2(__float2half_ru(bx.z), __float2half_ru(bx.w));
                g_meta [b][p] = make_uint4((unsigned)(key & 0xFFFFFFFFu),
                                           (unsigned)(key >> 32),
                                           *reinterpret_cast<unsigned*>(&p01),
                                           *reinterpret_cast<unsigned*>(&p23));
                g_boxes[b][p] = bx;
                g_area [b][p] = box_area(bx);
                g_score[b][p] = s;
            }
        }
    }
}

// ---------------- kernel 2: ranks + sparse conflict pairs (4 rows/warp, 1 load/pair-quad) ----------------
// grid: (CAP/32, BATCHB), block 256 = 8 warps; each warp owns 4 consecutive rows.
__global__ void __launch_bounds__(256) k_rankpairs()
{
    const int b    = blockIdx.y;
    const int warp = threadIdx.x >> 5;
    const int lane = threadIdx.x & 31;

    int cand = g_counters[b]; if (cand > CAP) cand = CAP;
    const int rowBase = (blockIdx.x * 8 + warp) * 4;
    if (rowBase >= cand) return;                      // warp-uniform exit

    // load row state into registers
    unsigned long long ki[4];
    float4 A[4];
    float  aA[4];
    int    rnk[4] = {0, 0, 0, 0};
    int    nrow = cand - rowBase; if (nrow > 4) nrow = 4;
    #pragma unroll
    for (int r = 0; r < 4; ++r) {
        int i = rowBase + (r < nrow ? r : 0);
        uint4 m = g_meta[b][i];
        ki[r] = (unsigned long long)m.x | ((unsigned long long)m.y << 32);
        A[r]  = g_boxes[b][i];
        aA[r] = g_area[b][i];
    }

    for (int jt = 0; jt < cand; jt += 32) {
        int j = jt + lane;                            // padding rows are inert (zero meta)
        uint4 m = g_meta[b][j];
        unsigned long long kj = (unsigned long long)m.x | ((unsigned long long)m.y << 32);
        __half2 h01 = *reinterpret_cast<__half2*>(&m.z);
        __half2 h23 = *reinterpret_cast<__half2*>(&m.w);
        float2 lo = __half22float2(h01);              // conservative (x1,y1)
        float2 hi = __half22float2(h23);              // conservative (x2,y2)

        #pragma unroll
        for (int r = 0; r < 4; ++r) {
            bool gt = (kj > ki[r]);
            unsigned bal = __ballot_sync(0xFFFFFFFFu, gt);
            rnk[r] += __popc(bal);
            // suppressor-direction + conservative overlap prefilter
            bool suspect = (!gt) && (j != rowBase + r) &&
                           (lo.x < A[r].z) && (A[r].x < hi.x) &&
                           (lo.y < A[r].w) && (A[r].y < hi.y);
            if (r < nrow && suspect) {
                float4 B = g_boxes[b][j];
                float aB = g_area[b][j];
                if (conflict_ref(A[r], aA[r], B, aB)) {
                    int p = atomicAdd(&g_counters[4 + b], 1);
                    if (p < PCAP)
                        g_pairs[b][p] = ((unsigned)(rowBase + r) << 16) | (unsigned)j;
                }
            }
        }
    }
    if (lane == 0) {
        #pragma unroll
        for (int r = 0; r < 4; ++r)
            if (r < nrow) g_rank[b][rowBase + r] = rnk[r];
    }
}

// ---------------- kernel 3: SPARSE greedy fixpoint + output (+ counter reset) ----------------
__global__ void __launch_bounds__(NT, 1) k_scan(float* __restrict__ out, int out_size)
{
    __shared__ int           rnk[CAP];
    __shared__ unsigned      spairs[PCAP];      // (rank_i << 16) | rank_j, rank_i < rank_j
    __shared__ unsigned char state[CAP];        // 0 = UNK, 1 = SELECTED, 2 = DEAD (by rank)
    __shared__ unsigned char hasLive[CAP];
    __shared__ unsigned      incW[NW];          // ranks with >=1 incoming pair
    __shared__ int           lst[CAP];          // compact list of contested ranks
    __shared__ int           sNt;
    __shared__ unsigned      selW[NW];
    __shared__ int           wordPref[NW];
    __shared__ int           sChanged;

    const int b   = blockIdx.x;
    const int tid = threadIdx.x;

    int cand = g_counters[b];     if (cand > CAP)  cand = CAP;
    int np   = g_counters[4 + b]; if (np   > PCAP) np   = PCAP;

    #pragma unroll
    for (int rep = 0; rep < CAP / NT; ++rep) {
        int u = tid + rep * NT;
        rnk[u]     = (u < cand) ? g_rank[b][u] : 0;
        state[u]   = (u < cand) ? 0 : 2;
        hasLive[u] = 0;
    }
    if (tid < NW) incW[tid] = 0u;
    if (tid == 0) sNt = 0;
    __syncthreads();

    // counters fully consumed -> reset for next graph replay
    if (tid == 0) { g_counters[b] = 0; g_counters[4 + b] = 0; }

    // re-encode pairs into rank space; mark ranks with incoming pairs
    for (int p = tid; p < np; p += NT) {
        unsigned pr = g_pairs[b][p];
        unsigned ri = (unsigned)rnk[pr >> 16];
        unsigned rj = (unsigned)rnk[pr & 0xFFFFu];
        spairs[p] = (ri << 16) | rj;
        atomicOr(&incW[rj >> 5], 1u << (rj & 31));
    }
    __syncthreads();

    // round 0: ranks with NO incoming pair are always selected
    #pragma unroll
    for (int rep = 0; rep < CAP / NT; ++rep) {
        int r = tid + rep * NT;
        if (r < cand && !((incW[r >> 5] >> (r & 31)) & 1u)) state[r] = 1;
    }
    // compact list of contested ranks (<= np entries)
    if (tid < NW) {
        unsigned w = incW[tid];
        while (w) {
            int bit = __ffs(w) - 1;
            w &= w - 1;
            int pos = atomicAdd(&sNt, 1);
            lst[pos] = tid * 32 + bit;
        }
    }
    __syncthreads();
    const int nt = sNt;

    // fixpoint over the contested subgraph.
    // SELECTED(j) <=> all suppressors DEAD; DEAD(j) <=> some suppressor SELECTED.
    // Suppressor rank < suppressed rank => DAG => unique fixpoint == greedy NMS.
    while (true) {
        if (tid == 0) sChanged = 0;
        for (int t = tid; t < nt; t += NT) hasLive[lst[t]] = 0;
        __syncthreads();

        for (int p = tid; p < np; p += NT) {
            unsigned pr = spairs[p];
            unsigned ri = pr >> 16, rj = pr & 0xFFFFu;
            if (state[ri] == 1 && state[rj] == 0) state[rj] = 2;
        }
        __syncthreads();

        for (int p = tid; p < np; p += NT) {
            unsigned pr = spairs[p];
            unsigned ri = pr >> 16, rj = pr & 0xFFFFu;
            if (state[rj] == 0 && state[ri] != 2) hasLive[rj] = 1;
        }
        __syncthreads();

        for (int t = tid; t < nt; t += NT) {
            int r = lst[t];
            if (state[r] == 0 && !hasLive[r]) { state[r] = 1; sChanged = 1; }
        }
        __syncthreads();
        if (!sChanged) break;
        __syncthreads();
    }

    // build selection bitmap over ranks (8 warps -> 8 words each)
    {
        int lane = tid & 31, wid = tid >> 5;
        #pragma unroll
        for (int rep = 0; rep < NW / (NT / 32); ++rep) {
            int w = wid + rep * (NT / 32);
            int r = w * 32 + lane;
            unsigned bal = __ballot_sync(0xFFFFFFFFu, state[r] == 1);
            if (lane == 0) selW[w] = bal;
        }
    }
    __syncthreads();
    if (tid == 0) {
        int run = 0;
        #pragma unroll
        for (int w = 0; w < NW; ++w) { wordPref[w] = run; run += __popc(selW[w]); }
    }
    __syncthreads();

    // ---- output: boxes [B,1000,4] | scores [B,1000] | valid [B,1000], all f32 ----
    const int scoresO = BATCHB * MAXD * 4;
    const int validO  = scoresO + BATCHB * MAXD;

    // zero-fill this image's slots
    for (int s = tid; s < MAXD; s += NT) {
        int bb = (b * MAXD + s) * 4;
        if (bb + 3 < out_size) {
            out[bb + 0] = 0.f; out[bb + 1] = 0.f;
            out[bb + 2] = 0.f; out[bb + 3] = 0.f;
        }
        int so = scoresO + b * MAXD + s;
        if (so < out_size) out[so] = 0.f;
        int vo = validO + b * MAXD + s;
        if (vo < out_size) out[vo] = 0.f;
    }
    __syncthreads();

    // emit selected: slot = rank order among selected (== reference selection order)
    #pragma unroll
    for (int rep = 0; rep < CAP / NT; ++rep) {
        int u = tid + rep * NT;
        if (u < cand) {
            int r = rnk[u];
            unsigned wbits = selW[r >> 5];
            if ((wbits >> (r & 31)) & 1u) {
                int slot = wordPref[r >> 5] + __popc(wbits & ((1u << (r & 31)) - 1u));
                if (slot < MAXD) {
                    float4 bx = g_boxes[b][u];
                    int bb = (b * MAXD + slot) * 4;
                    if (bb + 3 < out_size) {
                        out[bb + 0] = bx.x;
                        out[bb + 1] = bx.y;
                        out[bb + 2] = bx.z;
                        out[bb + 3] = bx.w;
                    }
                    int so = scoresO + b * MAXD + slot;
                    if (so < out_size) out[so] = g_score[b][u];
                    int vo = validO + b * MAXD + slot;
                    if (vo < out_size) out[vo] = 1.0f;
                }
            }
        }
    }
}

// ---------------- host launcher: 3 plain nodes (R5 structure) ----------------
extern "C" void kernel_launch(void* const* d_in, const int* in_sizes, int n_in,
                              void* d_out, int out_size)
{
    const float* obj     = (const float*)d_in[0];
    const float* deltas  = (const float*)d_in[1];
    const float* anchors = (const float*)d_in[2];
    float* out = (float*)d_out;

    // counters: zero at process start (static init); k_scan re-zeros each run.

    // 1) gather + decode
    {
        dim3 grid(NQUAD / 256, BATCHB);     // exact fit: 225 x 4
        k_gather<<<grid, 256>>>(obj, deltas, anchors);
    }

    // 2) ranks + sparse conflict pairs (4 rows/warp, fp16 prefilter)
    {
        dim3 grid(CAP / 32, BATCHB);        // 64 x 4
        k_rankpairs<<<grid, 256>>>();
    }

    // 3) sparse greedy fixpoint + output
    k_scan<<<BATCHB, NT>>>(out, out_size);
}

// round 15
// speedup vs baseline: 1.2886x; 1.2886x over previous
#include <cuda_runtime.h>
#include <cuda_fp16.h>
#include <cstdint>

// ---------------- problem constants ----------------
#define BATCHB   4
#define NANCH    230400        // 160*160*9
#define NQUAD    (NANCH/4)     // 57600 float4 quads per image (225 blocks * 256 exact)
#define CAP      2048          // candidate capacity per image
#define NW       (CAP/32)      // 64 bitmap words
#define PCAP     4096          // conflict-pair capacity per image (~15x expected)
#define MAXD     1000
#define IMGW     1280.0f
#define TH_IOU   0.5f
#define ZTH      2.45f         // raw objectness gather threshold (sigmoid monotone)
#define NT       256

// ---------------- device scratch (no allocations allowed) ----------------
// g_meta: {key_lo, key_hi, half2(x1,y1) rounded-down, half2(x2,y2) rounded-up}
// zero-init padding is inert: key=0 never outranks, zero half-box fails the prefilter.
__device__ uint4    g_meta [BATCHB][CAP];
__device__ float4   g_boxes[BATCHB][CAP];             // fp32 decoded boxes
__device__ float    g_area [BATCHB][CAP];
__device__ float    g_score[BATCHB][CAP];
__device__ int      g_rank [BATCHB][CAP];             // rank (0 = best) per unsorted slot
__device__ unsigned g_pairs[BATCHB][PCAP];            // (i<<16)|j, key_i > key_j (i = suppressor)
__device__ int      g_counters[8];                    // [0..3] cand, [4..7] pairs (zero-init; k_scan resets)

// ---------------- helpers ----------------
__device__ __forceinline__ float4 decode_box(float4 d, float4 a) {
    float w  = a.z - a.x;
    float h  = a.w - a.y;
    float cx = a.x + 0.5f * w;
    float cy = a.y + 0.5f * h;
    float px = fmaf(d.x, w, cx);
    float py = fmaf(d.y, h, cy);
    float pw = expf(fminf(d.z, 4.0f)) * w;
    float ph = expf(fminf(d.w, 4.0f)) * h;
    float x1 = px - 0.5f * pw;
    float y1 = py - 0.5f * ph;
    float x2 = px + 0.5f * pw;
    float y2 = py + 0.5f * ph;
    x1 = fminf(fmaxf(x1, 0.0f), IMGW);
    x2 = fminf(fmaxf(x2, 0.0f), IMGW);
    y1 = fminf(fmaxf(y1, 0.0f), IMGW);
    y2 = fminf(fmaxf(y2, 0.0f), IMGW);
    return make_float4(x1, y1, x2, y2);
}

__device__ __forceinline__ float box_area(float4 b) {
    return fmaxf(b.z - b.x, 0.0f) * fmaxf(b.w - b.y, 0.0f);
}

// exact reference IoU decision: inter/(aA + aB - inter + 1e-9) > 0.5
// A/aA MUST be the suppressor (earlier-ranked) box to match operand order.
__device__ __forceinline__ bool conflict_ref(float4 A, float aA, float4 B, float aB) {
    float ix1 = fmaxf(A.x, B.x);
    float iy1 = fmaxf(A.y, B.y);
    float ix2 = fminf(A.z, B.z);
    float iy2 = fminf(A.w, B.w);
    float iw = ix2 - ix1, ih = iy2 - iy1;
    if (iw > 0.0f && ih > 0.0f) {
        float inter = iw * ih;
        return (inter / (aA + aB - inter + 1e-9f)) > TH_IOU;
    }
    return false;
}

// XLA expands lax.logistic as 0.5 + 0.5*tanh(0.5*x)
__device__ __forceinline__ float sigmoid_xla(float x) {
    return 0.5f + 0.5f * tanhf(0.5f * x);
}

// read the 64-bit key from packed meta (defined BEFORE first use)
__device__ __forceinline__ unsigned long long meta_key(int b, int i) {
    uint4 m = g_meta[b][i];
    return (unsigned long long)m.x | ((unsigned long long)m.y << 32);
}

// ---------------- kernel 1: gather + decode (4 anchors/thread, float4 reads) ----------------
// EXACT R5 shape.
__global__ void __launch_bounds__(256) k_gather(
    const float* __restrict__ obj,
    const float* __restrict__ deltas,
    const float* __restrict__ anchors)
{
    int b  = blockIdx.y;
    int q  = blockIdx.x * blockDim.x + threadIdx.x;   // quad index (exact fit 225*256)
    float4 xs = reinterpret_cast<const float4*>(obj + (long)b * NANCH)[q];
    float xv[4] = {xs.x, xs.y, xs.z, xs.w};

    #pragma unroll
    for (int k = 0; k < 4; ++k) {
        float x = xv[k];
        if (x <= ZTH) continue;
        int i = q * 4 + k;
        long base = ((long)b * NANCH + i);
        float4 d = reinterpret_cast<const float4*>(deltas)[base];
        float4 a = reinterpret_cast<const float4*>(anchors)[base];
        float4 bx = decode_box(d, a);
        if ((bx.z - bx.x >= 1.0f) && (bx.w - bx.y >= 1.0f)) {
            float s = sigmoid_xla(x);
            unsigned sb = __float_as_uint(s);       // positive float: bits monotone
            unsigned long long key =
                ((unsigned long long)sb << 18) | (unsigned long long)(0x3FFFFu - (unsigned)i);
            int p = atomicAdd(&g_counters[b], 1);
            if (p < CAP) {
                // conservative fp16 box: lo rounded down, hi rounded up
                __half2 p01 = __halves2half2(__float2half_rd(bx.x), __float2half_rd(bx.y));
                __half2 p23 = __halves2half2(__float2half_ru(bx.z), __float2half_ru(bx.w));
                g_meta [b][p] = make_uint4((unsigned)(key & 0xFFFFFFFFu),
                                           (unsigned)(key >> 32),
                                           *reinterpret_cast<unsigned*>(&p01),
                                           *reinterpret_cast<unsigned*>(&p23));
                g_boxes[b][p] = bx;
                g_area [b][p] = box_area(bx);
                g_score[b][p] = s;
            }
        }
    }
}

// ---------------- kernel 2: ranks + sparse conflict pairs ----------------
// EXACT R5 shape: grid (CAP/8, BATCHB), 256 threads = 8 warps, warp w owns row i.
// NEW: single uint4 meta load per lane-iteration + conservative fp16 prefilter;
// exact IoU only for ~2% suspects (provably a superset of true conflicts).
__global__ void __launch_bounds__(256) k_rankpairs()
{
    const int b    = blockIdx.y;
    const int warp = threadIdx.x >> 5;
    const int lane = threadIdx.x & 31;

    int cand = g_counters[b]; if (cand > CAP) cand = CAP;
    const int i = blockIdx.x * 8 + warp;
    if (i >= cand) return;

    const unsigned long long ki = meta_key(b, i);
    const float4 A  = g_boxes[b][i];
    const float  aA = g_area[b][i];

    int rank = 0;
    for (int jt = 0; jt < cand; jt += 32) {
        int j = jt + lane;                            // j < CAP always; padding inert
        uint4 m = g_meta[b][j];
        unsigned long long kj =
            (unsigned long long)m.x | ((unsigned long long)m.y << 32);
        bool gt = (kj > ki);
        rank += __popc(__ballot_sync(0xFFFFFFFFu, gt));

        // conservative overlap prefilter on the packed fp16 box
        __half2 h01 = *reinterpret_cast<__half2*>(&m.z);
        __half2 h23 = *reinterpret_cast<__half2*>(&m.w);
        float2 lo = __half22float2(h01);              // (x1,y1) rounded down
        float2 hi = __half22float2(h23);              // (x2,y2) rounded up
        bool suspect = (!gt) && (j != i) &&
                       (lo.x < A.z) && (A.x < hi.x) &&
                       (lo.y < A.w) && (A.y < hi.y);
        if (suspect) {
            float4 B = g_boxes[b][j];
            float aB = g_area[b][j];
            if (conflict_ref(A, aA, B, aB)) {
                int p = atomicAdd(&g_counters[4 + b], 1);
                if (p < PCAP)
                    g_pairs[b][p] = ((unsigned)i << 16) | (unsigned)j;
            }
        }
    }
    if (lane == 0) g_rank[b][i] = rank;
}

// ---------------- kernel 3: SPARSE greedy fixpoint + output (+ counter reset) ----------------
__global__ void __launch_bounds__(NT, 1) k_scan(float* __restrict__ out, int out_size)
{
    __shared__ int           rnk[CAP];
    __shared__ unsigned      spairs[PCAP];      // (rank_i << 16) | rank_j, rank_i < rank_j
    __shared__ unsigned char state[CAP];        // 0 = UNK, 1 = SELECTED, 2 = DEAD (by rank)
    __shared__ unsigned char hasLive[CAP];
    __shared__ unsigned      incW[NW];          // ranks with >=1 incoming pair
    __shared__ int           lst[CAP];          // compact list of contested ranks
    __shared__ int           sNt;
    __shared__ unsigned      selW[NW];
    __shared__ int           wordPref[NW];
    __shared__ int           sChanged;

    const int b   = blockIdx.x;
    const int tid = threadIdx.x;

    int cand = g_counters[b];     if (cand > CAP)  cand = CAP;
    int np   = g_counters[4 + b]; if (np   > PCAP) np   = PCAP;

    #pragma unroll
    for (int rep = 0; rep < CAP / NT; ++rep) {
        int u = tid + rep * NT;
        rnk[u]     = (u < cand) ? g_rank[b][u] : 0;
        state[u]   = (u < cand) ? 0 : 2;
        hasLive[u] = 0;
    }
    if (tid < NW) incW[tid] = 0u;
    if (tid == 0) sNt = 0;
    __syncthreads();

    // counters fully consumed -> reset for next graph replay
    if (tid == 0) { g_counters[b] = 0; g_counters[4 + b] = 0; }

    // re-encode pairs into rank space; mark ranks with incoming pairs
    for (int p = tid; p < np; p += NT) {
        unsigned pr = g_pairs[b][p];
        unsigned ri = (unsigned)rnk[pr >> 16];
        unsigned rj = (unsigned)rnk[pr & 0xFFFFu];
        spairs[p] = (ri << 16) | rj;
        atomicOr(&incW[rj >> 5], 1u << (rj & 31));
    }
    __syncthreads();

    // round 0: ranks with NO incoming pair are always selected
    #pragma unroll
    for (int rep = 0; rep < CAP / NT; ++rep) {
        int r = tid + rep * NT;
        if (r < cand && !((incW[r >> 5] >> (r & 31)) & 1u)) state[r] = 1;
    }
    // compact list of contested ranks (<= np entries)
    if (tid < NW) {
        unsigned w = incW[tid];
        while (w) {
            int bit = __ffs(w) - 1;
            w &= w - 1;
            int pos = atomicAdd(&sNt, 1);
            lst[pos] = tid * 32 + bit;
        }
    }
    __syncthreads();
    const int nt = sNt;

    // fixpoint over the contested subgraph.
    // SELECTED(j) <=> all suppressors DEAD; DEAD(j) <=> some suppressor SELECTED.
    // Suppressor rank < suppressed rank => DAG => unique fixpoint == greedy NMS.
    while (true) {
        if (tid == 0) sChanged = 0;
        for (int t = tid; t < nt; t += NT) hasLive[lst[t]] = 0;
        __syncthreads();

        for (int p = tid; p < np; p += NT) {
            unsigned pr = spairs[p];
            unsigned ri = pr >> 16, rj = pr & 0xFFFFu;
            if (state[ri] == 1 && state[rj] == 0) state[rj] = 2;
        }
        __syncthreads();

        for (int p = tid; p < np; p += NT) {
            unsigned pr = spairs[p];
            unsigned ri = pr >> 16, rj = pr & 0xFFFFu;
            if (state[rj] == 0 && state[ri] != 2) hasLive[rj] = 1;
        }
        __syncthreads();

        for (int t = tid; t < nt; t += NT) {
            int r = lst[t];
            if (state[r] == 0 && !hasLive[r]) { state[r] = 1; sChanged = 1; }
        }
        __syncthreads();
        if (!sChanged) break;
        __syncthreads();
    }

    // build selection bitmap over ranks (8 warps -> 8 words each)
    {
        int lane = tid & 31, wid = tid >> 5;
        #pragma unroll
        for (int rep = 0; rep < NW / (NT / 32); ++rep) {
            int w = wid + rep * (NT / 32);
            int r = w * 32 + lane;
            unsigned bal = __ballot_sync(0xFFFFFFFFu, state[r] == 1);
            if (lane == 0) selW[w] = bal;
        }
    }
    __syncthreads();
    if (tid == 0) {
        int run = 0;
        #pragma unroll
        for (int w = 0; w < NW; ++w) { wordPref[w] = run; run += __popc(selW[w]); }
    }
    __syncthreads();

    // ---- output: boxes [B,1000,4] | scores [B,1000] | valid [B,1000], all f32 ----
    const int scoresO = BATCHB * MAXD * 4;
    const int validO  = scoresO + BATCHB * MAXD;

    // zero-fill this image's slots
    for (int s = tid; s < MAXD; s += NT) {
        int bb = (b * MAXD + s) * 4;
        if (bb + 3 < out_size) {
            out[bb + 0] = 0.f; out[bb + 1] = 0.f;
            out[bb + 2] = 0.f; out[bb + 3] = 0.f;
        }
        int so = scoresO + b * MAXD + s;
        if (so < out_size) out[so] = 0.f;
        int vo = validO + b * MAXD + s;
        if (vo < out_size) out[vo] = 0.f;
    }
    __syncthreads();

    // emit selected: slot = rank order among selected (== reference selection order)
    #pragma unroll
    for (int rep = 0; rep < CAP / NT; ++rep) {
        int u = tid + rep * NT;
        if (u < cand) {
            int r = rnk[u];
            unsigned wbits = selW[r >> 5];
            if ((wbits >> (r & 31)) & 1u) {
                int slot = wordPref[r >> 5] + __popc(wbits & ((1u << (r & 31)) - 1u));
                if (slot < MAXD) {
                    float4 bx = g_boxes[b][u];
                    int bb = (b * MAXD + slot) * 4;
                    if (bb + 3 < out_size) {
                        out[bb + 0] = bx.x;
                        out[bb + 1] = bx.y;
                        out[bb + 2] = bx.z;
                        out[bb + 3] = bx.w;
                    }
                    int so = scoresO + b * MAXD + slot;
                    if (so < out_size) out[so] = g_score[b][u];
                    int vo = validO + b * MAXD + slot;
                    if (vo < out_size) out[vo] = 1.0f;
                }
            }
        }
    }
}

// ---------------- host launcher: 3 plain nodes (R5 structure) ----------------
extern "C" void kernel_launch(void* const* d_in, const int* in_sizes, int n_in,
                              void* d_out, int out_size)
{
    const float* obj     = (const float*)d_in[0];
    const float* deltas  = (const float*)d_in[1];
    const float* anchors = (const float*)d_in[2];
    float* out = (float*)d_out;

    // counters: zero at process start (static init); k_scan re-zeros each run.

    // 1) gather + decode
    {
        dim3 grid(NQUAD / 256, BATCHB);     // exact fit: 225 x 4
        k_gather<<<grid, 256>>>(obj, deltas, anchors);
    }

    // 2) ranks + sparse conflict pairs (1 row/warp + fp16 prefilter)
    {
        dim3 grid(CAP / 8, BATCHB);         // 256 x 4 = 2048 warps
        k_rankpairs<<<grid, 256>>>();
    }

    // 3) sparse greedy fixpoint + output
    k_scan<<<BATCHB, NT>>>(out, out_size);
}